// round 7
// baseline (speedup 1.0000x reference)
#include <cuda_runtime.h>
#include <cuda_bf16.h>

// y = D @ x per row, D = blockdiag(1024 x [4x4]) + diag(rem[3]).
// x: (16384, 4099) fp32. Row stride 4099 ≡ 3 (mod 4).
//  * RPC=4, row0=4*by -> misalignment per row is static: {0,3,2,1}.
//  * All bulk traffic is aligned LDG.128 / STG.128.
//  * NEW (R7): interior warp-boundary outputs exchanged through shared memory
//    (lane31 v-quad -> next warp's lane0) so interior lanes always issue full
//    STG.128. Only warp0-lane0 / warp7-lane31 keep CTA-boundary scalars,
//    preserving the inter-CTA write contract of R6.

#define BS     4
#define GPC    256   // groups per CTA == blockDim.x
#define NWARPS 8
#define RPC    4

struct W4 { float4 w0, w1, w2, w3; };

__device__ __forceinline__ float4 apply_w(const W4& w,
                                          float x0, float x1, float x2, float x3)
{
    float4 o;
    o.x = w.w0.x*x0 + w.w0.y*x1 + w.w0.z*x2 + w.w0.w*x3;
    o.y = w.w1.x*x0 + w.w1.y*x1 + w.w1.z*x2 + w.w1.w*x3;
    o.z = w.w2.x*x0 + w.w2.y*x1 + w.w2.z*x2 + w.w2.w*x3;
    o.w = w.w3.x*x0 + w.w3.y*x1 + w.w3.z*x2 + w.w3.w*x3;
    return o;
}

// Compute this thread's 4 outputs for a row with compile-time misalignment R.
template<int R>
__device__ __forceinline__ float4 compute_v(float4 q, float4 p, int lane, const W4& w)
{
    float nx = __shfl_down_sync(0xffffffffu, q.x, 1);
    float ny = __shfl_down_sync(0xffffffffu, q.y, 1);
    float nz = __shfl_down_sync(0xffffffffu, q.z, 1);
    if (lane == 31) { nx = p.x; ny = p.y; nz = p.z; }
    float x0, x1, x2, x3;
    if (R == 1)      { x0 = q.y; x1 = q.z; x2 = q.w; x3 = nx; }
    else if (R == 2) { x0 = q.z; x1 = q.w; x2 = nx;  x3 = ny; }
    else             { x0 = q.w; x1 = nx;  x2 = ny;  x3 = nz; }
    return apply_w(w, x0, x1, x2, x3);
}

// Merge with predecessor tail (shfl within warp; smem value for lane0) and store.
// prev_tail is the PREVIOUS warp's lane31 v-quad (valid when lane==0 && warp>0).
template<int R>
__device__ __forceinline__ void merge_store(
    float4 v, float4 prev_tail, int s, int lane, int warp, float* __restrict__ y)
{
    float p1 = __shfl_up_sync(0xffffffffu, v.y, 1);
    float p2 = __shfl_up_sync(0xffffffffu, v.z, 1);
    float p3 = __shfl_up_sync(0xffffffffu, v.w, 1);
    if (lane == 0) { p1 = prev_tail.y; p2 = prev_tail.z; p3 = prev_tail.w; }

    float4 o;
    if (R == 1)      { o.x = p3; o.y = v.x; o.z = v.y; o.w = v.z; }
    else if (R == 2) { o.x = p2; o.y = p3; o.z = v.x; o.w = v.y; }
    else             { o.x = p1; o.y = p2; o.z = p3; o.w = v.x; }

    if (!(lane == 0 && warp == 0)) {
        __stcs(reinterpret_cast<float4*>(y + (s - R)) + lane, o);
    } else {
        // CTA leading boundary: write only own logical elements
        y[s + 0] = v.x;
        if (R < 3) y[s + 1] = v.y;
        if (R < 2) y[s + 2] = v.z;
    }
    if (lane == 31 && warp == NWARPS - 1) {
        // CTA trailing boundary: own logical tail not covered by aligned quads
        y[s + 127] = v.w;
        if (R >= 2) y[s + 126] = v.z;
        if (R >= 3) y[s + 125] = v.y;
    }
}

__global__ void __launch_bounds__(256, 4) block_apply_vec5_kernel(
    const float* __restrict__ x,
    const float* __restrict__ blocks,
    const float* __restrict__ dr,
    float* __restrict__ y,
    int n_blocks, int rem, int row_len, int total_rows)
{
    __shared__ float4 xch[3][NWARPS];

    const int tid  = threadIdx.x;
    const int lane = tid & 31;
    const int warp = tid >> 5;
    const int g    = blockIdx.x * GPC + tid;

    W4 w;
    {
        const float4* bp = reinterpret_cast<const float4*>(blocks) + g * BS;
        w.w0 = __ldg(bp + 0); w.w1 = __ldg(bp + 1);
        w.w2 = __ldg(bp + 2); w.w3 = __ldg(bp + 3);
    }

    const int row0 = blockIdx.y * RPC;                    // multiple of 4
    const int warp_col0 = blockIdx.x * (GPC * BS) + (tid & ~31) * BS;
    const int s0 = row0 * row_len + warp_col0;            // s0 & 3 == 0

    if (row0 + RPC <= total_rows) {
        // static r pattern rows 0..3: {0,3,2,1}
        const float4* a0 = reinterpret_cast<const float4*>(x + s0);
        const float4* a1 = reinterpret_cast<const float4*>(x + s0 +     row_len - 3);
        const float4* a2 = reinterpret_cast<const float4*>(x + s0 + 2 * row_len - 2);
        const float4* a3 = reinterpret_cast<const float4*>(x + s0 + 3 * row_len - 1);

        // ---- load phase: everything in flight before compute ----
        float4 q0 = __ldcs(a0 + lane);
        float4 q1 = __ldcs(a1 + lane);
        float4 q2 = __ldcs(a2 + lane);
        float4 q3 = __ldcs(a3 + lane);
        float4 p1 = {0,0,0,0}, p2 = {0,0,0,0}, p3 = {0,0,0,0};
        if (lane == 31) {
            p1 = __ldcs(a1 + 32);
            p2 = __ldcs(a2 + 32);
            p3 = __ldcs(a3 + 32);
        }

        // row 0 (r=0): clean path
        {
            float4 o = apply_w(w, q0.x, q0.y, q0.z, q0.w);
            __stcs(reinterpret_cast<float4*>(y + s0) + lane, o);
        }

        // misaligned rows: compute v, exchange lane31 tails through smem
        float4 v1 = compute_v<3>(q1, p1, lane, w);
        float4 v2 = compute_v<2>(q2, p2, lane, w);
        float4 v3 = compute_v<1>(q3, p3, lane, w);

        if (lane == 31) {
            xch[0][warp] = v1;
            xch[1][warp] = v2;
            xch[2][warp] = v3;
        }
        __syncthreads();

        float4 t1 = {0,0,0,0}, t2 = {0,0,0,0}, t3 = {0,0,0,0};
        if (lane == 0 && warp > 0) {
            t1 = xch[0][warp - 1];
            t2 = xch[1][warp - 1];
            t3 = xch[2][warp - 1];
        }

        merge_store<3>(v1, t1, s0 +     row_len, lane, warp, y);
        merge_store<2>(v2, t2, s0 + 2 * row_len, lane, warp, y);
        merge_store<1>(v3, t3, s0 + 3 * row_len, lane, warp, y);
    } else {
        // generic tail rows (not hit for 16384 rows): scalar per-group path
        for (int row = row0; row < total_rows; ++row) {
            int base = row * row_len + g * BS;
            float4 o = apply_w(w, x[base+0], x[base+1], x[base+2], x[base+3]);
            y[base+0] = o.x; y[base+1] = o.y; y[base+2] = o.z; y[base+3] = o.w;
        }
    }

    // fused remainder duty: last column-CTA handles the diagonal tail
    if (blockIdx.x == gridDim.x - 1) {
        const int colbase = n_blocks * BS;
        const int tail = row_len - colbase;                 // == rem here
        const int row1 = min(row0 + RPC, total_rows);
        const int nrows = row1 - row0;
        const int tot = tail * nrows;
        for (int t = tid; t < tot; t += blockDim.x) {
            int rr = t / tail;
            int k  = t - rr * tail;
            int idx = (row0 + rr) * row_len + colbase + k;
            y[idx] = (k < rem) ? x[idx] * __ldg(dr + k) : 0.0f;
        }
    }
}

// Fallback for general shapes: thread owns a block, scalar path.
__global__ void __launch_bounds__(256) block_apply_simple_kernel(
    const float* __restrict__ x, const float* __restrict__ blocks,
    const float* __restrict__ dr, float* __restrict__ y,
    int n_blocks, int rem, int row_len, int total_rows, int rows_per_cta)
{
    const int b = blockIdx.x * blockDim.x + threadIdx.x;
    int row0 = blockIdx.y * rows_per_cta;
    int row1 = min(row0 + rows_per_cta, total_rows);
    if (b < n_blocks) {
        const float4* bp = reinterpret_cast<const float4*>(blocks) + b * BS;
        W4 w; w.w0 = __ldg(bp+0); w.w1 = __ldg(bp+1);
              w.w2 = __ldg(bp+2); w.w3 = __ldg(bp+3);
        int base = row0 * row_len + b * BS;
        for (int row = row0; row < row1; ++row, base += row_len) {
            float4 o = apply_w(w, x[base+0], x[base+1], x[base+2], x[base+3]);
            y[base+0] = o.x; y[base+1] = o.y; y[base+2] = o.z; y[base+3] = o.w;
        }
    } else if (b == n_blocks) {
        const int colbase = n_blocks * BS;
        const int tail = row_len - colbase;
        int base = row0 * row_len + colbase;
        for (int row = row0; row < row1; ++row, base += row_len)
            for (int t = 0; t < tail; ++t)
                y[base + t] = (t < rem) ? x[base + t] * __ldg(dr + t) : 0.0f;
    }
}

extern "C" void kernel_launch(void* const* d_in, const int* in_sizes, int n_in,
                              void* d_out, int out_size)
{
    const float* x      = (const float*)d_in[0];
    const float* blocks = (const float*)d_in[1];
    const float* dr     = (const float*)d_in[2];
    float* y = (float*)d_out;

    const int n_blocks     = in_sizes[1] / (BS * BS);   // 1024
    const int rem          = in_sizes[2];               // 3
    const int block_region = n_blocks * BS;             // 4096
    const int row_len      = block_region + rem;        // 4099
    const int total_rows   = out_size / row_len;        // 16384

    if (n_blocks % GPC == 0 && (row_len & 3) == 3) {
        const int gx = n_blocks / GPC;                              // 4
        const int gy = (total_rows + RPC - 1) / RPC;                // 4096
        dim3 grid(gx, gy, 1);
        block_apply_vec5_kernel<<<grid, GPC>>>(x, blocks, dr, y,
                                               n_blocks, rem, row_len, total_rows);
    } else {
        const int THREADS = 256;
        const int rows_per_cta = 8;
        dim3 grid((n_blocks + 1 + THREADS - 1) / THREADS,
                  (total_rows + rows_per_cta - 1) / rows_per_cta, 1);
        block_apply_simple_kernel<<<grid, THREADS>>>(x, blocks, dr, y,
                                                     n_blocks, rem, row_len,
                                                     total_rows, rows_per_cta);
    }
}

// round 9
// speedup vs baseline: 1.0747x; 1.0747x over previous
#include <cuda_runtime.h>
#include <cuda_bf16.h>

// y = D @ x per row, D = blockdiag(1024 x [4x4]) + diag(rem[3]).
// x: (16384, 4099) fp32. Row stride 4099 ≡ 3 (mod 4).
// Structure = R6 winner + two upgrades:
//  * r pattern per 4-row batch is static {0,3,2,1}. NEW: the r==2 row is
//    8-byte aligned -> direct LDG.64/STG.64 at the logical address: no
//    shuffles, no patch load, no edge scalars (same wavefront count as f4).
//  * RPC=8 (two static 4-row batches per CTA): halves per-CTA weight-load
//    overhead and remainder-duty cost.

#define BS     4
#define GPC    256   // groups per CTA == blockDim.x
#define NWARPS 8
#define RPC    8     // rows per CTA (two batches of 4)

struct W4 { float4 w0, w1, w2, w3; };

__device__ __forceinline__ float4 apply_w(const W4& w,
                                          float x0, float x1, float x2, float x3)
{
    float4 o;
    o.x = w.w0.x*x0 + w.w0.y*x1 + w.w0.z*x2 + w.w0.w*x3;
    o.y = w.w1.x*x0 + w.w1.y*x1 + w.w1.z*x2 + w.w1.w*x3;
    o.z = w.w2.x*x0 + w.w2.y*x1 + w.w2.z*x2 + w.w2.w*x3;
    o.w = w.w3.x*x0 + w.w3.y*x1 + w.w3.z*x2 + w.w3.w*x3;
    return o;
}

// One row with compile-time misalignment R (1 or 3), R6-style:
// q = lane's aligned quad at (s-R)+4*lane; p = lane31 patch quad at (s-R)+128.
template<int R>
__device__ __forceinline__ void process_row_shfl(
    float4 q, float4 p, int s, int lane, const W4& w, float* __restrict__ y)
{
    float nx = __shfl_down_sync(0xffffffffu, q.x, 1);
    float ny = __shfl_down_sync(0xffffffffu, q.y, 1);
    float nz = __shfl_down_sync(0xffffffffu, q.z, 1);
    if (lane == 31) { nx = p.x; ny = p.y; nz = p.z; }

    float x0, x1, x2, x3;
    if (R == 1)      { x0 = q.y; x1 = q.z; x2 = q.w; x3 = nx; }
    else             { x0 = q.w; x1 = nx;  x2 = ny;  x3 = nz; }   // R == 3

    float4 v = apply_w(w, x0, x1, x2, x3);

    float p1 = __shfl_up_sync(0xffffffffu, v.y, 1);
    float p2 = __shfl_up_sync(0xffffffffu, v.z, 1);
    float p3 = __shfl_up_sync(0xffffffffu, v.w, 1);
    float4 o;
    if (R == 1)      { o.x = p3; o.y = v.x; o.z = v.y; o.w = v.z; }
    else             { o.x = p1; o.y = p2; o.z = p3; o.w = v.x; }  // R == 3

    if (lane > 0) {
        __stcs(reinterpret_cast<float4*>(y + (s - R)) + lane, o);
    } else {
        y[s + 0] = v.x;
        if (R < 3) { y[s + 1] = v.y; y[s + 2] = v.z; }
    }
    if (lane == 31) {
        y[s + 127] = v.w;
        if (R >= 3) { y[s + 126] = v.z; y[s + 125] = v.y; }
    }
}

// One static 4-row batch starting at flat offset s0 (s0 % 4 == 0).
// r per row: {0, 3, 2, 1}.
__device__ __forceinline__ void process_batch4(
    const float* __restrict__ x, float* __restrict__ y,
    int s0, int row_len, int lane, const W4& w)
{
    const float4* a0 = reinterpret_cast<const float4*>(x + s0);
    const float4* a1 = reinterpret_cast<const float4*>(x + s0 +     row_len - 3);
    const float2* a2 = reinterpret_cast<const float2*>(x + s0 + 2 * row_len + 4 * lane);
    const float4* a3 = reinterpret_cast<const float4*>(x + s0 + 3 * row_len - 1);

    // ---- load phase: all rows in flight before compute ----
    float4 q0 = __ldcs(a0 + lane);
    float4 q1 = __ldcs(a1 + lane);
    float2 q2l = __ldcs(a2 + 0);
    float2 q2h = __ldcs(a2 + 1);
    float4 q3 = __ldcs(a3 + lane);
    float4 p1 = {0,0,0,0}, p3 = {0,0,0,0};
    if (lane == 31) {
        p1 = __ldcs(a1 + 32);
        p3 = __ldcs(a3 + 32);
    }

    // row +0 (r=0): clean float4
    {
        float4 o = apply_w(w, q0.x, q0.y, q0.z, q0.w);
        __stcs(reinterpret_cast<float4*>(y + s0) + lane, o);
    }
    // row +1 (r=3): shuffle path
    process_row_shfl<3>(q1, p1, s0 + row_len, lane, w, y);
    // row +2 (r=2): direct 8B-aligned float2 path — no shuffles, no edges
    {
        float4 o = apply_w(w, q2l.x, q2l.y, q2h.x, q2h.y);
        float2* ob = reinterpret_cast<float2*>(y + s0 + 2 * row_len + 4 * lane);
        __stcs(ob + 0, make_float2(o.x, o.y));
        __stcs(ob + 1, make_float2(o.z, o.w));
    }
    // row +3 (r=1): shuffle path
    process_row_shfl<1>(q3, p3, s0 + 3 * row_len, lane, w, y);
}

__global__ void __launch_bounds__(256, 4) block_apply_vec6_kernel(
    const float* __restrict__ x,
    const float* __restrict__ blocks,
    const float* __restrict__ dr,
    float* __restrict__ y,
    int n_blocks, int rem, int row_len, int total_rows)
{
    const int tid  = threadIdx.x;
    const int lane = tid & 31;
    const int g    = blockIdx.x * GPC + tid;

    W4 w;
    {
        const float4* bp = reinterpret_cast<const float4*>(blocks) + g * BS;
        w.w0 = __ldg(bp + 0); w.w1 = __ldg(bp + 1);
        w.w2 = __ldg(bp + 2); w.w3 = __ldg(bp + 3);
    }

    const int row0 = blockIdx.y * RPC;                    // multiple of 4
    const int warp_col0 = blockIdx.x * (GPC * BS) + (tid & ~31) * BS;

    if (row0 + RPC <= total_rows) {
        int s0 = row0 * row_len + warp_col0;              // s0 % 4 == 0
        process_batch4(x, y, s0, row_len, lane, w);
        process_batch4(x, y, s0 + 4 * row_len, row_len, lane, w);
    } else {
        // generic tail rows: scalar per-group path
        for (int row = row0; row < total_rows; ++row) {
            int base = row * row_len + g * BS;
            float4 o = apply_w(w, x[base+0], x[base+1], x[base+2], x[base+3]);
            y[base+0] = o.x; y[base+1] = o.y; y[base+2] = o.z; y[base+3] = o.w;
        }
    }

    // fused remainder duty: last column-CTA handles the diagonal tail
    if (blockIdx.x == gridDim.x - 1) {
        const int colbase = n_blocks * BS;
        const int tail = row_len - colbase;                 // == rem here
        const int row1 = min(row0 + RPC, total_rows);
        const int nrows = row1 - row0;
        const int tot = tail * nrows;
        for (int t = tid; t < tot; t += blockDim.x) {
            int rr = t / tail;
            int k  = t - rr * tail;
            int idx = (row0 + rr) * row_len + colbase + k;
            y[idx] = (k < rem) ? x[idx] * __ldg(dr + k) : 0.0f;
        }
    }
}

// Fallback for general shapes: thread owns a block, scalar path.
__global__ void __launch_bounds__(256) block_apply_simple_kernel(
    const float* __restrict__ x, const float* __restrict__ blocks,
    const float* __restrict__ dr, float* __restrict__ y,
    int n_blocks, int rem, int row_len, int total_rows, int rows_per_cta)
{
    const int b = blockIdx.x * blockDim.x + threadIdx.x;
    int row0 = blockIdx.y * rows_per_cta;
    int row1 = min(row0 + rows_per_cta, total_rows);
    if (b < n_blocks) {
        const float4* bp = reinterpret_cast<const float4*>(blocks) + b * BS;
        W4 w; w.w0 = __ldg(bp+0); w.w1 = __ldg(bp+1);
              w.w2 = __ldg(bp+2); w.w3 = __ldg(bp+3);
        int base = row0 * row_len + b * BS;
        for (int row = row0; row < row1; ++row, base += row_len) {
            float4 o = apply_w(w, x[base+0], x[base+1], x[base+2], x[base+3]);
            y[base+0] = o.x; y[base+1] = o.y; y[base+2] = o.z; y[base+3] = o.w;
        }
    } else if (b == n_blocks) {
        const int colbase = n_blocks * BS;
        const int tail = row_len - colbase;
        int base = row0 * row_len + colbase;
        for (int row = row0; row < row1; ++row, base += row_len)
            for (int t = 0; t < tail; ++t)
                y[base + t] = (t < rem) ? x[base + t] * __ldg(dr + t) : 0.0f;
    }
}

extern "C" void kernel_launch(void* const* d_in, const int* in_sizes, int n_in,
                              void* d_out, int out_size)
{
    const float* x      = (const float*)d_in[0];
    const float* blocks = (const float*)d_in[1];
    const float* dr     = (const float*)d_in[2];
    float* y = (float*)d_out;

    const int n_blocks     = in_sizes[1] / (BS * BS);   // 1024
    const int rem          = in_sizes[2];               // 3
    const int block_region = n_blocks * BS;             // 4096
    const int row_len      = block_region + rem;        // 4099
    const int total_rows   = out_size / row_len;        // 16384

    if (n_blocks % GPC == 0 && (row_len & 3) == 3) {
        const int gx = n_blocks / GPC;                              // 4
        const int gy = (total_rows + RPC - 1) / RPC;                // 2048
        dim3 grid(gx, gy, 1);
        block_apply_vec6_kernel<<<grid, GPC>>>(x, blocks, dr, y,
                                               n_blocks, rem, row_len, total_rows);
    } else {
        const int THREADS = 256;
        const int rows_per_cta = 8;
        dim3 grid((n_blocks + 1 + THREADS - 1) / THREADS,
                  (total_rows + rows_per_cta - 1) / rows_per_cta, 1);
        block_apply_simple_kernel<<<grid, THREADS>>>(x, blocks, dr, y,
                                                     n_blocks, rem, row_len,
                                                     total_rows, rows_per_cta);
    }
}

// round 12
// speedup vs baseline: 1.0784x; 1.0034x over previous
#include <cuda_runtime.h>
#include <cuda_bf16.h>

// y = D @ x per row, D = blockdiag(1024 x [4x4]) + diag(rem[3]).
// x: (16384, 4099) fp32. Row stride 4099 ≡ 3 (mod 4).
// R9 winner + software pipelining:
//  * static r pattern {0,3,2,1} per 4-row batch; r==2 row via 8B-aligned
//    LDG.64/STG.64 (no shuffles/edges); r==1,3 via shuffle realignment.
//  * NEW (R10): both 4-row batches' loads issued BEFORE any compute/store
//    -> ~10 in-flight LDG.128/thread across the whole compute phase.
//    launch_bounds(256,3) gives the register headroom (no spills).

#define BS     4
#define GPC    256   // groups per CTA == blockDim.x
#define RPC    8     // rows per CTA (two static batches of 4)

struct W4 { float4 w0, w1, w2, w3; };

// All loads for one 4-row batch.
struct B4 {
    float4 q0, q1, q3;     // aligned quads for rows r=0,3,1
    float2 q2l, q2h;       // 8B-aligned pair for row r=2
    float4 p1, p3;         // lane31 patch quads for rows r=3,1
};

__device__ __forceinline__ float4 apply_w(const W4& w,
                                          float x0, float x1, float x2, float x3)
{
    float4 o;
    o.x = w.w0.x*x0 + w.w0.y*x1 + w.w0.z*x2 + w.w0.w*x3;
    o.y = w.w1.x*x0 + w.w1.y*x1 + w.w1.z*x2 + w.w1.w*x3;
    o.z = w.w2.x*x0 + w.w2.y*x1 + w.w2.z*x2 + w.w2.w*x3;
    o.w = w.w3.x*x0 + w.w3.y*x1 + w.w3.z*x2 + w.w3.w*x3;
    return o;
}

template<int R>  // R in {1,3}
__device__ __forceinline__ void process_row_shfl(
    float4 q, float4 p, int s, int lane, const W4& w, float* __restrict__ y)
{
    float nx = __shfl_down_sync(0xffffffffu, q.x, 1);
    float ny = __shfl_down_sync(0xffffffffu, q.y, 1);
    float nz = __shfl_down_sync(0xffffffffu, q.z, 1);
    if (lane == 31) { nx = p.x; ny = p.y; nz = p.z; }

    float x0, x1, x2, x3;
    if (R == 1) { x0 = q.y; x1 = q.z; x2 = q.w; x3 = nx; }
    else        { x0 = q.w; x1 = nx;  x2 = ny;  x3 = nz; }   // R == 3

    float4 v = apply_w(w, x0, x1, x2, x3);

    float p1 = __shfl_up_sync(0xffffffffu, v.y, 1);
    float p2 = __shfl_up_sync(0xffffffffu, v.z, 1);
    float p3 = __shfl_up_sync(0xffffffffu, v.w, 1);
    float4 o;
    if (R == 1) { o.x = p3; o.y = v.x; o.z = v.y; o.w = v.z; }
    else        { o.x = p1; o.y = p2; o.z = p3; o.w = v.x; }   // R == 3

    if (lane > 0) {
        __stcs(reinterpret_cast<float4*>(y + (s - R)) + lane, o);
    } else {
        y[s + 0] = v.x;
        if (R < 3) { y[s + 1] = v.y; y[s + 2] = v.z; }
    }
    if (lane == 31) {
        y[s + 127] = v.w;
        if (R >= 3) { y[s + 126] = v.z; y[s + 125] = v.y; }
    }
}

__device__ __forceinline__ void load_batch4(
    const float* __restrict__ x, int s0, int row_len, int lane, B4& b)
{
    const float4* a0 = reinterpret_cast<const float4*>(x + s0);
    const float4* a1 = reinterpret_cast<const float4*>(x + s0 +     row_len - 3);
    const float2* a2 = reinterpret_cast<const float2*>(x + s0 + 2 * row_len + 4 * lane);
    const float4* a3 = reinterpret_cast<const float4*>(x + s0 + 3 * row_len - 1);

    b.q0  = __ldcs(a0 + lane);
    b.q1  = __ldcs(a1 + lane);
    b.q2l = __ldcs(a2 + 0);
    b.q2h = __ldcs(a2 + 1);
    b.q3  = __ldcs(a3 + lane);
    if (lane == 31) {
        b.p1 = __ldcs(a1 + 32);
        b.p3 = __ldcs(a3 + 32);
    }
}

__device__ __forceinline__ void store_batch4(
    float* __restrict__ y, const B4& b, int s0, int row_len, int lane, const W4& w)
{
    // row +0 (r=0): clean float4
    {
        float4 o = apply_w(w, b.q0.x, b.q0.y, b.q0.z, b.q0.w);
        __stcs(reinterpret_cast<float4*>(y + s0) + lane, o);
    }
    // row +1 (r=3)
    process_row_shfl<3>(b.q1, b.p1, s0 + row_len, lane, w, y);
    // row +2 (r=2): direct 8B-aligned float2 path
    {
        float4 o = apply_w(w, b.q2l.x, b.q2l.y, b.q2h.x, b.q2h.y);
        float2* ob = reinterpret_cast<float2*>(y + s0 + 2 * row_len + 4 * lane);
        __stcs(ob + 0, make_float2(o.x, o.y));
        __stcs(ob + 1, make_float2(o.z, o.w));
    }
    // row +3 (r=1)
    process_row_shfl<1>(b.q3, b.p3, s0 + 3 * row_len, lane, w, y);
}

__global__ void __launch_bounds__(256, 3) block_apply_vec7_kernel(
    const float* __restrict__ x,
    const float* __restrict__ blocks,
    const float* __restrict__ dr,
    float* __restrict__ y,
    int n_blocks, int rem, int row_len, int total_rows)
{
    const int tid  = threadIdx.x;
    const int lane = tid & 31;
    const int g    = blockIdx.x * GPC + tid;

    W4 w;
    {
        const float4* bp = reinterpret_cast<const float4*>(blocks) + g * BS;
        w.w0 = __ldg(bp + 0); w.w1 = __ldg(bp + 1);
        w.w2 = __ldg(bp + 2); w.w3 = __ldg(bp + 3);
    }

    const int row0 = blockIdx.y * RPC;                    // multiple of 4
    const int warp_col0 = blockIdx.x * (GPC * BS) + (tid & ~31) * BS;

    if (row0 + RPC <= total_rows) {
        const int s0 = row0 * row_len + warp_col0;        // s0 % 4 == 0
        const int s1 = s0 + 4 * row_len;

        // ---- pipelined load phase: BOTH batches in flight ----
        B4 b0, b1;
        load_batch4(x, s0, row_len, lane, b0);
        load_batch4(x, s1, row_len, lane, b1);

        // ---- compute/store phase ----
        store_batch4(y, b0, s0, row_len, lane, w);
        store_batch4(y, b1, s1, row_len, lane, w);
    } else {
        // generic tail rows: scalar per-group path
        for (int row = row0; row < total_rows; ++row) {
            int base = row * row_len + g * BS;
            float4 o = apply_w(w, x[base+0], x[base+1], x[base+2], x[base+3]);
            y[base+0] = o.x; y[base+1] = o.y; y[base+2] = o.z; y[base+3] = o.w;
        }
    }

    // fused remainder duty: last column-CTA handles the diagonal tail
    if (blockIdx.x == gridDim.x - 1) {
        const int colbase = n_blocks * BS;
        const int tail = row_len - colbase;                 // == rem here
        const int row1 = min(row0 + RPC, total_rows);
        const int nrows = row1 - row0;
        const int tot = tail * nrows;
        for (int t = tid; t < tot; t += blockDim.x) {
            int rr = t / tail;
            int k  = t - rr * tail;
            int idx = (row0 + rr) * row_len + colbase + k;
            y[idx] = (k < rem) ? x[idx] * __ldg(dr + k) : 0.0f;
        }
    }
}

// Fallback for general shapes: thread owns a block, scalar path.
__global__ void __launch_bounds__(256) block_apply_simple_kernel(
    const float* __restrict__ x, const float* __restrict__ blocks,
    const float* __restrict__ dr, float* __restrict__ y,
    int n_blocks, int rem, int row_len, int total_rows, int rows_per_cta)
{
    const int b = blockIdx.x * blockDim.x + threadIdx.x;
    int row0 = blockIdx.y * rows_per_cta;
    int row1 = min(row0 + rows_per_cta, total_rows);
    if (b < n_blocks) {
        const float4* bp = reinterpret_cast<const float4*>(blocks) + b * BS;
        W4 w; w.w0 = __ldg(bp+0); w.w1 = __ldg(bp+1);
              w.w2 = __ldg(bp+2); w.w3 = __ldg(bp+3);
        int base = row0 * row_len + b * BS;
        for (int row = row0; row < row1; ++row, base += row_len) {
            float4 o = apply_w(w, x[base+0], x[base+1], x[base+2], x[base+3]);
            y[base+0] = o.x; y[base+1] = o.y; y[base+2] = o.z; y[base+3] = o.w;
        }
    } else if (b == n_blocks) {
        const int colbase = n_blocks * BS;
        const int tail = row_len - colbase;
        int base = row0 * row_len + colbase;
        for (int row = row0; row < row1; ++row, base += row_len)
            for (int t = 0; t < tail; ++t)
                y[base + t] = (t < rem) ? x[base + t] * __ldg(dr + t) : 0.0f;
    }
}

extern "C" void kernel_launch(void* const* d_in, const int* in_sizes, int n_in,
                              void* d_out, int out_size)
{
    const float* x      = (const float*)d_in[0];
    const float* blocks = (const float*)d_in[1];
    const float* dr     = (const float*)d_in[2];
    float* y = (float*)d_out;

    const int n_blocks     = in_sizes[1] / (BS * BS);   // 1024
    const int rem          = in_sizes[2];               // 3
    const int block_region = n_blocks * BS;             // 4096
    const int row_len      = block_region + rem;        // 4099
    const int total_rows   = out_size / row_len;        // 16384

    if (n_blocks % GPC == 0 && (row_len & 3) == 3) {
        const int gx = n_blocks / GPC;                              // 4
        const int gy = (total_rows + RPC - 1) / RPC;                // 2048
        dim3 grid(gx, gy, 1);
        block_apply_vec7_kernel<<<grid, GPC>>>(x, blocks, dr, y,
                                               n_blocks, rem, row_len, total_rows);
    } else {
        const int THREADS = 256;
        const int rows_per_cta = 8;
        dim3 grid((n_blocks + 1 + THREADS - 1) / THREADS,
                  (total_rows + rows_per_cta - 1) / rows_per_cta, 1);
        block_apply_simple_kernel<<<grid, THREADS>>>(x, blocks, dr, y,
                                                     n_blocks, rem, row_len,
                                                     total_rows, rows_per_cta);
    }
}

// round 13
// speedup vs baseline: 1.0951x; 1.0155x over previous
#include <cuda_runtime.h>
#include <cuda_bf16.h>

// y = D @ x per row, D = blockdiag(1024 x [4x4]) + diag(rem[3]).
// x: (16384, 4099) fp32. Row stride 4099 ≡ 3 (mod 4).
// R9 structure (two sequential static 4-row batches, RPC=8) with trimmed
// shuffle dataflow:
//  * r pattern {0,3,2,1}: r=0 clean f4; r=2 direct 8B-aligned f2 (no shfl);
//    r=3 full shuffle path (6 shfl, f4 patch);
//    r=1 NEEDS ONLY 2 shuffles and a SCALAR patch (nx in, p3 out).
//  * launch_bounds(256,4): regs back under 64 -> 4 CTAs/SM.

#define BS     4
#define GPC    256   // groups per CTA == blockDim.x
#define RPC    8     // rows per CTA (two static batches of 4)

struct W4 { float4 w0, w1, w2, w3; };

__device__ __forceinline__ float4 apply_w(const W4& w,
                                          float x0, float x1, float x2, float x3)
{
    float4 o;
    o.x = w.w0.x*x0 + w.w0.y*x1 + w.w0.z*x2 + w.w0.w*x3;
    o.y = w.w1.x*x0 + w.w1.y*x1 + w.w1.z*x2 + w.w1.w*x3;
    o.z = w.w2.x*x0 + w.w2.y*x1 + w.w2.z*x2 + w.w2.w*x3;
    o.w = w.w3.x*x0 + w.w3.y*x1 + w.w3.z*x2 + w.w3.w*x3;
    return o;
}

// R == 3 row: q at (s-3)+4*lane, p = lane31 patch quad x[(s-3)+128 ..].
__device__ __forceinline__ void process_row_r3(
    float4 q, float4 p, int s, int lane, const W4& w, float* __restrict__ y)
{
    float nx = __shfl_down_sync(0xffffffffu, q.x, 1);
    float ny = __shfl_down_sync(0xffffffffu, q.y, 1);
    float nz = __shfl_down_sync(0xffffffffu, q.z, 1);
    if (lane == 31) { nx = p.x; ny = p.y; nz = p.z; }

    float4 v = apply_w(w, q.w, nx, ny, nz);

    float p1 = __shfl_up_sync(0xffffffffu, v.y, 1);
    float p2 = __shfl_up_sync(0xffffffffu, v.z, 1);
    float p3 = __shfl_up_sync(0xffffffffu, v.w, 1);
    float4 o; o.x = p1; o.y = p2; o.z = p3; o.w = v.x;

    if (lane > 0) {
        __stcs(reinterpret_cast<float4*>(y + (s - 3)) + lane, o);
    } else {
        y[s + 0] = v.x;
    }
    if (lane == 31) {
        y[s + 125] = v.y; y[s + 126] = v.z; y[s + 127] = v.w;
    }
}

// R == 1 row: q at (s-1)+4*lane, px = lane31 scalar patch x[s+127].
// Only 2 shuffles needed: nx in, carried tail out.
__device__ __forceinline__ void process_row_r1(
    float4 q, float px, int s, int lane, const W4& w, float* __restrict__ y)
{
    float nx = __shfl_down_sync(0xffffffffu, q.x, 1);
    if (lane == 31) nx = px;

    float4 v = apply_w(w, q.y, q.z, q.w, nx);

    float p3 = __shfl_up_sync(0xffffffffu, v.w, 1);
    float4 o; o.x = p3; o.y = v.x; o.z = v.y; o.w = v.z;

    if (lane > 0) {
        __stcs(reinterpret_cast<float4*>(y + (s - 1)) + lane, o);
    } else {
        y[s + 0] = v.x; y[s + 1] = v.y; y[s + 2] = v.z;
    }
    if (lane == 31) {
        y[s + 127] = v.w;
    }
}

// One static 4-row batch starting at flat offset s0 (s0 % 4 == 0).
// r per row: {0, 3, 2, 1}.
__device__ __forceinline__ void process_batch4(
    const float* __restrict__ x, float* __restrict__ y,
    int s0, int row_len, int lane, const W4& w)
{
    const float4* a0 = reinterpret_cast<const float4*>(x + s0);
    const float4* a1 = reinterpret_cast<const float4*>(x + s0 +     row_len - 3);
    const float2* a2 = reinterpret_cast<const float2*>(x + s0 + 2 * row_len + 4 * lane);
    const float4* a3 = reinterpret_cast<const float4*>(x + s0 + 3 * row_len - 1);

    // ---- load phase: all rows in flight before compute ----
    float4 q0 = __ldcs(a0 + lane);
    float4 q1 = __ldcs(a1 + lane);
    float2 q2l = __ldcs(a2 + 0);
    float2 q2h = __ldcs(a2 + 1);
    float4 q3 = __ldcs(a3 + lane);
    float4 p1 = {0,0,0,0};
    float  p3x = 0.0f;
    if (lane == 31) {
        p1  = __ldg(a1 + 32);                       // f4 patch (x,y,z used)
        p3x = __ldg(x + s0 + 3 * row_len + 127);    // scalar patch for r=1 row
    }

    // row +0 (r=0): clean float4
    {
        float4 o = apply_w(w, q0.x, q0.y, q0.z, q0.w);
        __stcs(reinterpret_cast<float4*>(y + s0) + lane, o);
    }
    // row +1 (r=3)
    process_row_r3(q1, p1, s0 + row_len, lane, w, y);
    // row +2 (r=2): direct 8B-aligned float2 path
    {
        float4 o = apply_w(w, q2l.x, q2l.y, q2h.x, q2h.y);
        float2* ob = reinterpret_cast<float2*>(y + s0 + 2 * row_len + 4 * lane);
        __stcs(ob + 0, make_float2(o.x, o.y));
        __stcs(ob + 1, make_float2(o.z, o.w));
    }
    // row +3 (r=1)
    process_row_r1(q3, p3x, s0 + 3 * row_len, lane, w, y);
}

__global__ void __launch_bounds__(256, 4) block_apply_vec8_kernel(
    const float* __restrict__ x,
    const float* __restrict__ blocks,
    const float* __restrict__ dr,
    float* __restrict__ y,
    int n_blocks, int rem, int row_len, int total_rows)
{
    const int tid  = threadIdx.x;
    const int lane = tid & 31;
    const int g    = blockIdx.x * GPC + tid;

    W4 w;
    {
        const float4* bp = reinterpret_cast<const float4*>(blocks) + g * BS;
        w.w0 = __ldg(bp + 0); w.w1 = __ldg(bp + 1);
        w.w2 = __ldg(bp + 2); w.w3 = __ldg(bp + 3);
    }

    const int row0 = blockIdx.y * RPC;                    // multiple of 4
    const int warp_col0 = blockIdx.x * (GPC * BS) + (tid & ~31) * BS;

    if (row0 + RPC <= total_rows) {
        int s0 = row0 * row_len + warp_col0;              // s0 % 4 == 0
        process_batch4(x, y, s0, row_len, lane, w);
        process_batch4(x, y, s0 + 4 * row_len, row_len, lane, w);
    } else {
        // generic tail rows: scalar per-group path
        for (int row = row0; row < total_rows; ++row) {
            int base = row * row_len + g * BS;
            float4 o = apply_w(w, x[base+0], x[base+1], x[base+2], x[base+3]);
            y[base+0] = o.x; y[base+1] = o.y; y[base+2] = o.z; y[base+3] = o.w;
        }
    }

    // fused remainder duty: last column-CTA handles the diagonal tail
    if (blockIdx.x == gridDim.x - 1) {
        const int colbase = n_blocks * BS;
        const int tail = row_len - colbase;                 // == rem here
        const int row1 = min(row0 + RPC, total_rows);
        const int nrows = row1 - row0;
        const int tot = tail * nrows;
        for (int t = tid; t < tot; t += blockDim.x) {
            int rr = t / tail;
            int k  = t - rr * tail;
            int idx = (row0 + rr) * row_len + colbase + k;
            y[idx] = (k < rem) ? x[idx] * __ldg(dr + k) : 0.0f;
        }
    }
}

// Fallback for general shapes: thread owns a block, scalar path.
__global__ void __launch_bounds__(256) block_apply_simple_kernel(
    const float* __restrict__ x, const float* __restrict__ blocks,
    const float* __restrict__ dr, float* __restrict__ y,
    int n_blocks, int rem, int row_len, int total_rows, int rows_per_cta)
{
    const int b = blockIdx.x * blockDim.x + threadIdx.x;
    int row0 = blockIdx.y * rows_per_cta;
    int row1 = min(row0 + rows_per_cta, total_rows);
    if (b < n_blocks) {
        const float4* bp = reinterpret_cast<const float4*>(blocks) + b * BS;
        W4 w; w.w0 = __ldg(bp+0); w.w1 = __ldg(bp+1);
              w.w2 = __ldg(bp+2); w.w3 = __ldg(bp+3);
        int base = row0 * row_len + b * BS;
        for (int row = row0; row < row1; ++row, base += row_len) {
            float4 o = apply_w(w, x[base+0], x[base+1], x[base+2], x[base+3]);
            y[base+0] = o.x; y[base+1] = o.y; y[base+2] = o.z; y[base+3] = o.w;
        }
    } else if (b == n_blocks) {
        const int colbase = n_blocks * BS;
        const int tail = row_len - colbase;
        int base = row0 * row_len + colbase;
        for (int row = row0; row < row1; ++row, base += row_len)
            for (int t = 0; t < tail; ++t)
                y[base + t] = (t < rem) ? x[base + t] * __ldg(dr + t) : 0.0f;
    }
}

extern "C" void kernel_launch(void* const* d_in, const int* in_sizes, int n_in,
                              void* d_out, int out_size)
{
    const float* x      = (const float*)d_in[0];
    const float* blocks = (const float*)d_in[1];
    const float* dr     = (const float*)d_in[2];
    float* y = (float*)d_out;

    const int n_blocks     = in_sizes[1] / (BS * BS);   // 1024
    const int rem          = in_sizes[2];               // 3
    const int block_region = n_blocks * BS;             // 4096
    const int row_len      = block_region + rem;        // 4099
    const int total_rows   = out_size / row_len;        // 16384

    if (n_blocks % GPC == 0 && (row_len & 3) == 3) {
        const int gx = n_blocks / GPC;                              // 4
        const int gy = (total_rows + RPC - 1) / RPC;                // 2048
        dim3 grid(gx, gy, 1);
        block_apply_vec8_kernel<<<grid, GPC>>>(x, blocks, dr, y,
                                               n_blocks, rem, row_len, total_rows);
    } else {
        const int THREADS = 256;
        const int rows_per_cta = 8;
        dim3 grid((n_blocks + 1 + THREADS - 1) / THREADS,
                  (total_rows + rows_per_cta - 1) / rows_per_cta, 1);
        block_apply_simple_kernel<<<grid, THREADS>>>(x, blocks, dr, y,
                                                     n_blocks, rem, row_len,
                                                     total_rows, rows_per_cta);
    }
}